// round 13
// baseline (speedup 1.0000x reference)
#include <cuda_runtime.h>
#include <math.h>

#define B_SZ   2
#define L_SZ   1024
#define DM     256
#define H_SZ   8
#define DK     32
#define NROWS  (B_SZ * L_SZ)            // 2048
#define INV_SQRT_DK 0.17677669529663687f

// -------- scratch (__device__ globals; no allocation allowed) --------
__device__ float g_hn  [NROWS * DM];
__device__ float g_q   [NROWS * DM];
__device__ float g_k   [NROWS * DM];
__device__ float g_v   [NROWS * DM];
__device__ float g_e1a [NROWS * DM];
__device__ float g_e1b [NROWS * DM];
__device__ float g_e1c [NROWS * DM];
__device__ float g_e1d [NROWS * DM];
__device__ float g_emb2[NROWS * DM];
__device__ float g_il  [H_SZ * NROWS];   // per (h,b,i) 1/l

// -------- f32x2 packed helpers --------
__device__ __forceinline__ unsigned long long pk2(float a, float b) {
    unsigned long long r;
    asm("mov.b64 %0, {%1, %2};" : "=l"(r) : "f"(a), "f"(b));
    return r;
}
__device__ __forceinline__ void upk2(unsigned long long v, float& a, float& b) {
    asm("mov.b64 {%0, %1}, %2;" : "=f"(a), "=f"(b) : "l"(v));
}
__device__ __forceinline__ unsigned long long ffma2(unsigned long long a,
                                                    unsigned long long b,
                                                    unsigned long long c) {
    unsigned long long d;
    asm("fma.rn.f32x2 %0, %1, %2, %3;" : "=l"(d) : "l"(a), "l"(b), "l"(c));
    return d;
}

// -------- L2 cache-policy helpers (cache_hint form) --------
__device__ __forceinline__ unsigned long long policy_evict_last() {
    unsigned long long pol;
    asm("createpolicy.fractional.L2::evict_last.b64 %0, 1.0;" : "=l"(pol));
    return pol;
}
__device__ __forceinline__ unsigned long long policy_evict_first() {
    unsigned long long pol;
    asm("createpolicy.fractional.L2::evict_first.b64 %0, 1.0;" : "=l"(pol));
    return pol;
}
__device__ __forceinline__ float4 ldg_hint4(const float* p, unsigned long long pol) {
    float4 v;
    asm volatile("ld.global.nc.L2::cache_hint.v4.f32 {%0,%1,%2,%3}, [%4], %5;"
        : "=f"(v.x), "=f"(v.y), "=f"(v.z), "=f"(v.w) : "l"(p), "l"(pol));
    return v;
}
__device__ __forceinline__ void stg_hint(float* p, float v, unsigned long long pol) {
    asm volatile("st.global.L2::cache_hint.f32 [%0], %1, %2;"
        :: "l"(p), "f"(v), "l"(pol) : "memory");
}
__device__ __forceinline__ void stg_hint4(float* p, float4 v, unsigned long long pol) {
    asm volatile("st.global.L2::cache_hint.v4.f32 [%0], {%1,%2,%3,%4}, %5;"
        :: "l"(p), "f"(v.x), "f"(v.y), "f"(v.z), "f"(v.w), "l"(pol) : "memory");
}

// ---------------------------------------------------------------
// LayerNorm
// ---------------------------------------------------------------
__global__ void ln_kernel(const float* __restrict__ hin,
                          const float* __restrict__ gam,
                          const float* __restrict__ bta)
{
    int row = blockIdx.x, tid = threadIdx.x;
    float x = hin[(size_t)row * DM + tid];
    float s1 = x, s2 = x * x;
    #pragma unroll
    for (int o = 16; o; o >>= 1) {
        s1 += __shfl_xor_sync(0xffffffffu, s1, o);
        s2 += __shfl_xor_sync(0xffffffffu, s2, o);
    }
    __shared__ float r1[8], r2[8];
    __shared__ float mu_s, rstd_s;
    if ((tid & 31) == 0) { r1[tid >> 5] = s1; r2[tid >> 5] = s2; }
    __syncthreads();
    if (tid == 0) {
        float a = 0.f, c = 0.f;
        #pragma unroll
        for (int i = 0; i < 8; i++) { a += r1[i]; c += r2[i]; }
        float mu  = a * (1.0f / DM);
        float var = c * (1.0f / DM) - mu * mu;
        mu_s = mu; rstd_s = rsqrtf(var + 1e-5f);
    }
    __syncthreads();
    g_hn[(size_t)row * DM + tid] = (x - mu_s) * rstd_s * gam[tid] + bta[tid];
}

// ---------------------------------------------------------------
// Fused QKV projection, f32x2, double-buffered k-loop. grid (12, 32)
// ---------------------------------------------------------------
__global__ void qkv_kernel(const float* __restrict__ w_qs,
                           const float* __restrict__ w_ks,
                           const float* __restrict__ w_vs)
{
    __shared__ float As[2][16][64];
    __shared__ float Bs[2][16][64];
    int tid = threadIdx.x;
    int sel = blockIdx.x >> 2;
    int n0  = (blockIdx.x & 3) * 64;
    int m0  = blockIdx.y * 64;
    const float* Bm = (sel == 0) ? w_qs : (sel == 1) ? w_ks : w_vs;
    float* C = (sel == 0) ? g_q : (sel == 1) ? g_k : g_v;
    float scale = (sel == 0) ? INV_SQRT_DK : 1.0f;

    int tx = tid & 15, ty = tid >> 4;
    int lr = tid >> 2, lc = (tid & 3) * 4;
    unsigned long long acc[4][2];
    #pragma unroll
    for (int i = 0; i < 4; i++) { acc[i][0] = 0ull; acc[i][1] = 0ull; }

    const float* Aptr = g_hn + (size_t)(m0 + lr) * DM + lc;
    const float* Bptr = Bm   + (size_t)(n0 + lr) * DM + lc;

    {
        float4 av = *(const float4*)Aptr;
        float4 bv = *(const float4*)Bptr;
        As[0][lc + 0][lr] = av.x; As[0][lc + 1][lr] = av.y; As[0][lc + 2][lr] = av.z; As[0][lc + 3][lr] = av.w;
        Bs[0][lc + 0][lr] = bv.x; Bs[0][lc + 1][lr] = bv.y; Bs[0][lc + 2][lr] = bv.z; Bs[0][lc + 3][lr] = bv.w;
    }
    __syncthreads();

    for (int t = 0; t < 16; t++) {
        int cur = t & 1;
        float4 av2, bv2;
        if (t < 15) {
            av2 = *(const float4*)(Aptr + (t + 1) * 16);
            bv2 = *(const float4*)(Bptr + (t + 1) * 16);
        }
        #pragma unroll
        for (int kk = 0; kk < 16; kk++) {
            float4 a = *(const float4*)&As[cur][kk][ty * 4];
            ulonglong2 b2 = *(const ulonglong2*)&Bs[cur][kk][tx * 4];
            unsigned long long ap;
            ap = pk2(a.x, a.x);
            acc[0][0] = ffma2(b2.x, ap, acc[0][0]);
            acc[0][1] = ffma2(b2.y, ap, acc[0][1]);
            ap = pk2(a.y, a.y);
            acc[1][0] = ffma2(b2.x, ap, acc[1][0]);
            acc[1][1] = ffma2(b2.y, ap, acc[1][1]);
            ap = pk2(a.z, a.z);
            acc[2][0] = ffma2(b2.x, ap, acc[2][0]);
            acc[2][1] = ffma2(b2.y, ap, acc[2][1]);
            ap = pk2(a.w, a.w);
            acc[3][0] = ffma2(b2.x, ap, acc[3][0]);
            acc[3][1] = ffma2(b2.y, ap, acc[3][1]);
        }
        if (t < 15) {
            int nx = cur ^ 1;
            As[nx][lc + 0][lr] = av2.x; As[nx][lc + 1][lr] = av2.y; As[nx][lc + 2][lr] = av2.z; As[nx][lc + 3][lr] = av2.w;
            Bs[nx][lc + 0][lr] = bv2.x; Bs[nx][lc + 1][lr] = bv2.y; Bs[nx][lc + 2][lr] = bv2.z; Bs[nx][lc + 3][lr] = bv2.w;
        }
        __syncthreads();
    }
    #pragma unroll
    for (int i = 0; i < 4; i++) {
        int m = m0 + ty * 4 + i;
        float r0, r1, r2, r3;
        upk2(acc[i][0], r0, r1);
        upk2(acc[i][1], r2, r3);
        float4 o = make_float4(r0 * scale, r1 * scale, r2 * scale, r3 * scale);
        *(float4*)(C + (size_t)m * DM + n0 + tx * 4) = o;
    }
}

// ---------------------------------------------------------------
// s1: raw attn1 = qhat . k for one batch b, f32x2, 64x64 tiles.
// Stores with evict_last so s2 reads hit L2. grid (16, 16, 8)
// ---------------------------------------------------------------
__global__ void s1_kernel(float* __restrict__ attn, int b)
{
    __shared__ float Qs[32][64];
    __shared__ float Ks[32][64];
    int tid = threadIdx.x;
    int h = blockIdx.z;
    int i0 = blockIdx.y * 64, j0 = blockIdx.x * 64;
    const unsigned long long POL_EL = policy_evict_last();

    {
        int r  = tid >> 2;
        int c4 = (tid & 3) * 8;
        const float* qp = g_q + ((size_t)(b * L_SZ) + i0 + r) * DM + h * DK + c4;
        const float* kp = g_k + ((size_t)(b * L_SZ) + j0 + r) * DM + h * DK + c4;
        float4 a0 = *(const float4*)qp, a1 = *(const float4*)(qp + 4);
        float4 c0 = *(const float4*)kp, c1 = *(const float4*)(kp + 4);
        Qs[c4 + 0][r] = a0.x; Qs[c4 + 1][r] = a0.y; Qs[c4 + 2][r] = a0.z; Qs[c4 + 3][r] = a0.w;
        Qs[c4 + 4][r] = a1.x; Qs[c4 + 5][r] = a1.y; Qs[c4 + 6][r] = a1.z; Qs[c4 + 7][r] = a1.w;
        Ks[c4 + 0][r] = c0.x; Ks[c4 + 1][r] = c0.y; Ks[c4 + 2][r] = c0.z; Ks[c4 + 3][r] = c0.w;
        Ks[c4 + 4][r] = c1.x; Ks[c4 + 5][r] = c1.y; Ks[c4 + 6][r] = c1.z; Ks[c4 + 7][r] = c1.w;
    }
    __syncthreads();

    int tx = tid & 15, ty = tid >> 4;
    unsigned long long acc[4][2];
    #pragma unroll
    for (int i = 0; i < 4; i++) { acc[i][0] = 0ull; acc[i][1] = 0ull; }

    #pragma unroll
    for (int kk = 0; kk < 32; kk++) {
        float4 a = *(const float4*)&Qs[kk][ty * 4];
        ulonglong2 c2 = *(const ulonglong2*)&Ks[kk][tx * 4];
        unsigned long long ap;
        ap = pk2(a.x, a.x);
        acc[0][0] = ffma2(c2.x, ap, acc[0][0]);
        acc[0][1] = ffma2(c2.y, ap, acc[0][1]);
        ap = pk2(a.y, a.y);
        acc[1][0] = ffma2(c2.x, ap, acc[1][0]);
        acc[1][1] = ffma2(c2.y, ap, acc[1][1]);
        ap = pk2(a.z, a.z);
        acc[2][0] = ffma2(c2.x, ap, acc[2][0]);
        acc[2][1] = ffma2(c2.y, ap, acc[2][1]);
        ap = pk2(a.w, a.w);
        acc[3][0] = ffma2(c2.x, ap, acc[3][0]);
        acc[3][1] = ffma2(c2.y, ap, acc[3][1]);
    }
    #pragma unroll
    for (int ii = 0; ii < 4; ii++) {
        int i = i0 + ty * 4 + ii;
        float4 r;
        upk2(acc[ii][0], r.x, r.y);
        upk2(acc[ii][1], r.z, r.w);
        stg_hint4(attn + ((size_t)((h * B_SZ + b) * L_SZ + i)) * L_SZ + j0 + tx * 4, r, POL_EL);
    }
}

// ---------------------------------------------------------------
// s2 fused for one batch b: 128-thread CTAs (2 rows x 2 halves).
// attn1 LDGs hoisted before staging; bias evict_first; p evict_last.
// grid 512 per batch.
// ---------------------------------------------------------------
#define BT_STRIDE 33
#define PS_STRIDE 12
__global__ void __launch_bounds__(128) s2_kernel(const float* __restrict__ bias,
                                                 float* __restrict__ attn, int b)
{
    extern __shared__ float sm4[];
    float* qp = sm4;                          // 512
    float* bt = sm4 + 512;                    // 4224
    float* ps = sm4 + 512 + 4224;             // 1536
    float* cl = sm4 + 512 + 4224 + 1536;      // 32
    float* co = cl + 32;                      // 512

    int tid = threadIdx.x;
    int w = tid >> 5, lane = tid & 31;
    int r0 = b * L_SZ + blockIdx.x * 2;
    const unsigned long long POL_EL = policy_evict_last();
    const unsigned long long POL_EF = policy_evict_first();

    for (int e = tid; e < 512; e += 128) {
        int row = e >> 8, x = e & 255, h = x >> 5, d = x & 31;
        qp[row * 256 + d * 8 + h] = g_q[(size_t)(r0 + row) * DM + x];
    }
    __syncthreads();

    int rl   = w >> 1;
    int half = w & 1;
    int r    = r0 + rl;

    const float* qprow = qp + rl * 256;
    float* btw = bt + w * (32 * BT_STRIDE);
    float* psw = ps + w * (32 * PS_STRIDE);

    const float* bsrc = bias + (size_t)r * L_SZ * DK;
    float* arow = attn + ((size_t)r << 10);

    unsigned long long lpk[4], o2pk[4];
    #pragma unroll
    for (int k = 0; k < 4; k++) { lpk[k] = 0ull; o2pk[k] = 0ull; }
    const unsigned long long ONE2 = pk2(1.0f, 1.0f);

    for (int jt = 0; jt < 16; jt++) {
        int j0 = half * 512 + jt * 32;

        // ---- hoisted attn1 loads (independent of staging; overlap) ----
        float s0 = arow[(0ull << 21) + j0 + lane];
        float s1 = arow[(1ull << 21) + j0 + lane];
        float s2v = arow[(2ull << 21) + j0 + lane];
        float s3 = arow[(3ull << 21) + j0 + lane];
        float s4 = arow[(4ull << 21) + j0 + lane];
        float s5 = arow[(5ull << 21) + j0 + lane];
        float s6 = arow[(6ull << 21) + j0 + lane];
        float s7 = arow[(7ull << 21) + j0 + lane];

        // ---- stage bias tile transposed: bt[d][j] ----
        #pragma unroll
        for (int it = 0; it < 8; it++) {
            int e  = it * 32 + lane;
            int jj = e >> 3;
            int c8 = e & 7;
            float4 v = ldg_hint4(bsrc + ((size_t)(j0 + jj) * 8 + c8) * 4, POL_EF);
            btw[(c8 * 4 + 0) * BT_STRIDE + jj] = v.x;
            btw[(c8 * 4 + 1) * BT_STRIDE + jj] = v.y;
            btw[(c8 * 4 + 2) * BT_STRIDE + jj] = v.z;
            btw[(c8 * 4 + 3) * BT_STRIDE + jj] = v.w;
        }
        __syncwarp();

        unsigned long long spk[4];
        spk[0] = pk2(s0, s1); spk[1] = pk2(s2v, s3);
        spk[2] = pk2(s4, s5); spk[3] = pk2(s6, s7);

        #pragma unroll
        for (int d = 0; d < 32; d++) {
            float bb = btw[d * BT_STRIDE + lane];
            unsigned long long bbp = pk2(bb, bb);
            ulonglong2 qA = *(const ulonglong2*)(qprow + d * 8);
            ulonglong2 qB = *(const ulonglong2*)(qprow + d * 8 + 4);
            spk[0] = ffma2(qA.x, bbp, spk[0]);
            spk[1] = ffma2(qA.y, bbp, spk[1]);
            spk[2] = ffma2(qB.x, bbp, spk[2]);
            spk[3] = ffma2(qB.y, bbp, spk[3]);
        }

        float p[8];
        {
            float a, b2;
            #pragma unroll
            for (int k = 0; k < 4; k++) {
                upk2(spk[k], a, b2);
                p[2 * k]     = __expf(a);
                p[2 * k + 1] = __expf(b2);
            }
            float4* pd = (float4*)(psw + lane * PS_STRIDE);
            pd[0] = make_float4(p[0], p[1], p[2], p[3]);
            pd[1] = make_float4(p[4], p[5], p[6], p[7]);
            #pragma unroll
            for (int h = 0; h < 8; h++)
                stg_hint(arow + ((unsigned long long)h << 21) + j0 + lane, p[h], POL_EL);
            #pragma unroll
            for (int k = 0; k < 4; k++)
                lpk[k] = ffma2(pk2(p[2 * k], p[2 * k + 1]), ONE2, lpk[k]);
        }
        __syncwarp();

        #pragma unroll 4
        for (int j = 0; j < 32; j++) {
            float bb = btw[lane * BT_STRIDE + j];
            unsigned long long bbp = pk2(bb, bb);
            ulonglong2 pv0 = *(const ulonglong2*)(psw + j * PS_STRIDE);
            ulonglong2 pv1 = *(const ulonglong2*)(psw + j * PS_STRIDE + 4);
            o2pk[0] = ffma2(pv0.x, bbp, o2pk[0]);
            o2pk[1] = ffma2(pv0.y, bbp, o2pk[1]);
            o2pk[2] = ffma2(pv1.x, bbp, o2pk[2]);
            o2pk[3] = ffma2(pv1.y, bbp, o2pk[3]);
        }
        __syncwarp();
    }

    float l[8], o2[8];
    #pragma unroll
    for (int k = 0; k < 4; k++) {
        upk2(lpk[k],  l[2 * k],  l[2 * k + 1]);
        upk2(o2pk[k], o2[2 * k], o2[2 * k + 1]);
    }
    #pragma unroll
    for (int h = 0; h < 8; h++) {
        float ls = l[h];
        #pragma unroll
        for (int o = 16; o; o >>= 1)
            ls += __shfl_xor_sync(0xffffffffu, ls, o);
        l[h] = ls;
    }

    if (lane == 0) {
        #pragma unroll
        for (int h = 0; h < 8; h++) cl[(rl * 2 + half) * 8 + h] = l[h];
    }
    if (half == 1) {
        #pragma unroll
        for (int h = 0; h < 8; h++) co[(rl * 8 + h) * 32 + lane] = o2[h];
    }
    __syncthreads();
    if (half == 0) {
        #pragma unroll
        for (int h = 0; h < 8; h++) {
            float ltot = cl[(rl * 2) * 8 + h] + cl[(rl * 2 + 1) * 8 + h];
            float invl = 1.0f / ltot;
            float ot = o2[h] + co[(rl * 8 + h) * 32 + lane];
            g_emb2[(size_t)r * DM + h * DK + lane] = ot * invl;
            if (lane == 0)
                g_il[h * NROWS + r] = invl;
        }
    }
}

// ---------------------------------------------------------------
// e1 for one batch b: double-buffered pipeline over a 256-j quarter.
// grid (16, 8, 4). Normalizes attn in place (evict_first).
// ---------------------------------------------------------------
__global__ void e1_kernel(float* __restrict__ attn, int b)
{
    __shared__ float At[2][32][65];
    __shared__ float Vs[2][32][36];
    int tid = threadIdx.x;
    int h  = blockIdx.y;
    int i0 = blockIdx.x * 64;
    int jq = blockIdx.z;
    float* eout = (jq == 0) ? g_e1a : (jq == 1) ? g_e1b : (jq == 2) ? g_e1c : g_e1d;
    int w = tid >> 5, lane = tid & 31;
    const unsigned long long POL_EF = policy_evict_first();

    int rr = tid >> 3;
    int jc = (tid & 7) * 4;
    float invl0 = g_il[h * NROWS + b * L_SZ + i0 + rr];
    float invl1 = g_il[h * NROWS + b * L_SZ + i0 + rr + 32];

    float* a0base = attn + ((size_t)((h * B_SZ + b) * L_SZ + i0 + rr)) * L_SZ + jq * 256 + jc;
    float* a1base = a0base + (size_t)32 * L_SZ;
    const float* vbase = g_v + ((size_t)(b * L_SZ) + jq * 256 + rr) * DM + h * DK + jc;

    unsigned long long acc[2][2];
    acc[0][0] = 0ull; acc[0][1] = 0ull; acc[1][0] = 0ull; acc[1][1] = 0ull;

    float4 a0r, a1r, vr;
    {
        float4 a = *(float4*)a0base;
        a.x *= invl0; a.y *= invl0; a.z *= invl0; a.w *= invl0;
        stg_hint4(a0base, a, POL_EF); a0r = a;
        float4 c = *(float4*)a1base;
        c.x *= invl1; c.y *= invl1; c.z *= invl1; c.w *= invl1;
        stg_hint4(a1base, c, POL_EF); a1r = c;
        vr = __ldg((const float4*)vbase);
    }
    At[0][jc + 0][rr] = a0r.x; At[0][jc + 1][rr] = a0r.y;
    At[0][jc + 2][rr] = a0r.z; At[0][jc + 3][rr] = a0r.w;
    At[0][jc + 0][rr + 32] = a1r.x; At[0][jc + 1][rr + 32] = a1r.y;
    At[0][jc + 2][rr + 32] = a1r.z; At[0][jc + 3][rr + 32] = a1r.w;
    *(float4*)&Vs[0][rr][jc] = vr;
    __syncthreads();

    for (int jt = 0; jt < 8; jt++) {
        int cur = jt & 1;
        if (jt < 7) {
            int off = (jt + 1) * 32;
            float4 a = *(float4*)(a0base + off);
            a.x *= invl0; a.y *= invl0; a.z *= invl0; a.w *= invl0;
            stg_hint4(a0base + off, a, POL_EF); a0r = a;
            float4 c = *(float4*)(a1base + off);
            c.x *= invl1; c.y *= invl1; c.z *= invl1; c.w *= invl1;
            stg_hint4(a1base + off, c, POL_EF); a1r = c;
            vr = __ldg((const float4*)(vbase + (size_t)off * DM));
        }
        #pragma unroll
        for (int kk = 0; kk < 32; kk++) {
            ulonglong2 v2 = *(const ulonglong2*)&Vs[cur][kk][w * 4];
            float a0 = At[cur][kk][lane];
            float a1 = At[cur][kk][lane + 32];
            unsigned long long ap0 = pk2(a0, a0);
            unsigned long long ap1 = pk2(a1, a1);
            acc[0][0] = ffma2(v2.x, ap0, acc[0][0]);
            acc[0][1] = ffma2(v2.y, ap0, acc[0][1]);
            acc[1][0] = ffma2(v2.x, ap1, acc[1][0]);
            acc[1][1] = ffma2(v2.y, ap1, acc[1][1]);
        }
        if (jt < 7) {
            int nx = cur ^ 1;
            At[nx][jc + 0][rr] = a0r.x; At[nx][jc + 1][rr] = a0r.y;
            At[nx][jc + 2][rr] = a0r.z; At[nx][jc + 3][rr] = a0r.w;
            At[nx][jc + 0][rr + 32] = a1r.x; At[nx][jc + 1][rr + 32] = a1r.y;
            At[nx][jc + 2][rr + 32] = a1r.z; At[nx][jc + 3][rr + 32] = a1r.w;
            *(float4*)&Vs[nx][rr][jc] = vr;
        }
        __syncthreads();
    }
    #pragma unroll
    for (int p = 0; p < 2; p++) {
        float4 o;
        upk2(acc[p][0], o.x, o.y);
        upk2(acc[p][1], o.z, o.w);
        *(float4*)(eout + ((size_t)(b * L_SZ) + i0 + lane + p * 32) * DM + h * DK + w * 4) = o;
    }
}

// ---------------------------------------------------------------
// fc: out = (e1a+e1b+e1c+e1d+emb2) @ fc_w^T + fc_b + residual
// ---------------------------------------------------------------
__global__ void fc_kernel(const float* __restrict__ Bm,
                          const float* __restrict__ fcb,
                          const float* __restrict__ res,
                          float* __restrict__ C)
{
    __shared__ float As[2][16][64];
    __shared__ float Bs[2][16][64];
    int tid = threadIdx.x;
    int tx = tid & 15, ty = tid >> 4;
    int m0 = blockIdx.y * 64, n0 = blockIdx.x * 64;
    int lr = tid >> 2, lc = (tid & 3) * 4;
    unsigned long long acc[4][2];
    #pragma unroll
    for (int i = 0; i < 4; i++) { acc[i][0] = 0ull; acc[i][1] = 0ull; }

    size_t abase = (size_t)(m0 + lr) * DM + lc;
    const float* Bptr = Bm + (size_t)(n0 + lr) * DM + lc;

    {
        float4 a1 = *(const float4*)(g_e1a + abase);
        float4 a3 = *(const float4*)(g_e1b + abase);
        float4 a4 = *(const float4*)(g_e1c + abase);
        float4 a5 = *(const float4*)(g_e1d + abase);
        float4 a2 = *(const float4*)(g_emb2 + abase);
        float4 bv = *(const float4*)Bptr;
        As[0][lc + 0][lr] = a1.x + a3.x + a4.x + a5.x + a2.x;
        As[0][lc + 1][lr] = a1.y + a3.y + a4.y + a5.y + a2.y;
        As[0][lc + 2][lr] = a1.z + a3.z + a4.z + a5.z + a2.z;
        As[0][lc + 3][lr] = a1.w + a3.w + a4.w + a5.w + a2.w;
        Bs[0][lc + 0][lr] = bv.x; Bs[0][lc + 1][lr] = bv.y; Bs[0][lc + 2][lr] = bv.z; Bs[0][lc + 3][lr] = bv.w;
    }
    __syncthreads();

    for (int t = 0; t < 16; t++) {
        int cur = t & 1;
        float4 asum, bv2;
        if (t < 15) {
            size_t aoff = abase + (t + 1) * 16;
            float4 a1 = *(const float4*)(g_e1a + aoff);
            float4 a3 = *(const float4*)(g_e1b + aoff);
            float4 a4 = *(const float4*)(g_e1c + aoff);
            float4 a5 = *(const float4*)(g_e1d + aoff);
            float4 a2 = *(const float4*)(g_emb2 + aoff);
            asum.x = a1.x + a3.x + a4.x + a5.x + a2.x;
            asum.y = a1.y + a3.y + a4.y + a5.y + a2.y;
            asum.z = a1.z + a3.z + a4.z + a5.z + a2.z;
            asum.w = a1.w + a3.w + a4.w + a5.w + a2.w;
            bv2 = *(const float4*)(Bptr + (t + 1) * 16);
        }
        #pragma unroll
        for (int kk = 0; kk < 16; kk++) {
            float4 a = *(const float4*)&As[cur][kk][ty * 4];
            ulonglong2 b2 = *(const ulonglong2*)&Bs[cur][kk][tx * 4];
            unsigned long long ap;
            ap = pk2(a.x, a.x);
            acc[0][0] = ffma2(b2.x, ap, acc[0][0]);
            acc[0][1] = ffma2(b2.y, ap, acc[0][1]);
            ap = pk2(a.y, a.y);
            acc[1][0] = ffma2(b2.x, ap, acc[1][0]);
            acc[1][1] = ffma2(b2.y, ap, acc[1][1]);
            ap = pk2(a.z, a.z);
            acc[2][0] = ffma2(b2.x, ap, acc[2][0]);
            acc[2][1] = ffma2(b2.y, ap, acc[2][1]);
            ap = pk2(a.w, a.w);
            acc[3][0] = ffma2(b2.x, ap, acc[3][0]);
            acc[3][1] = ffma2(b2.y, ap, acc[3][1]);
        }
        if (t < 15) {
            int nx = cur ^ 1;
            As[nx][lc + 0][lr] = asum.x; As[nx][lc + 1][lr] = asum.y;
            As[nx][lc + 2][lr] = asum.z; As[nx][lc + 3][lr] = asum.w;
            Bs[nx][lc + 0][lr] = bv2.x; Bs[nx][lc + 1][lr] = bv2.y;
            Bs[nx][lc + 2][lr] = bv2.z; Bs[nx][lc + 3][lr] = bv2.w;
        }
        __syncthreads();
    }
    #pragma unroll
    for (int i = 0; i < 4; i++) {
        int m = m0 + ty * 4 + i;
        float r0, r1, r2, r3;
        upk2(acc[i][0], r0, r1);
        upk2(acc[i][1], r2, r3);
        int n = n0 + tx * 4;
        const float4 rv = *(const float4*)(res + (size_t)m * DM + n);
        const float4 bb = *(const float4*)(fcb + n);
        float4 o;
        o.x = r0 + bb.x + rv.x;
        o.y = r1 + bb.y + rv.y;
        o.z = r2 + bb.z + rv.z;
        o.w = r3 + bb.w + rv.w;
        *(float4*)(C + (size_t)m * DM + n) = o;
    }
}

// ---------------------------------------------------------------
extern "C" void kernel_launch(void* const* d_in, const int* in_sizes, int n_in,
                              void* d_out, int out_size)
{
    const float* h    = (const float*)d_in[0];
    const float* bias = (const float*)d_in[1];
    const float* w_qs = (const float*)d_in[2];
    const float* w_ks = (const float*)d_in[3];
    const float* w_vs = (const float*)d_in[4];
    const float* ln_g = (const float*)d_in[5];
    const float* ln_b = (const float*)d_in[6];
    const float* fc_w = (const float*)d_in[7];
    const float* fc_b = (const float*)d_in[8];

    float* out  = (float*)d_out;                       // (B, L, 256)
    float* attn = out + (size_t)B_SZ * L_SZ * DM;      // (H, B, L, L)

    const int SMEM_S2 = (512 + 4224 + 1536 + 32 + 512) * sizeof(float);  // 27264 B
    cudaFuncSetAttribute(s2_kernel, cudaFuncAttributeMaxDynamicSharedMemorySize, SMEM_S2);

    // 1. LayerNorm
    ln_kernel<<<NROWS, 256>>>(h, ln_g, ln_b);

    // 2. QKV projections (q pre-scaled), double-buffered
    qkv_kernel<<<dim3(12, NROWS / 64), 256>>>(w_qs, w_ks, w_vs);

    // 3-5. per-batch pipeline: keeps attn1(b)+p(b) (66 MB) L2-resident
    for (int b = 0; b < B_SZ; b++) {
        s1_kernel<<<dim3(16, 16, 8), 256>>>(attn, b);
        s2_kernel<<<L_SZ / 2, 128, SMEM_S2>>>(bias, attn, b);
        e1_kernel<<<dim3(16, 8, 4), 256>>>(attn, b);
    }

    // 6. out = (e1a+e1b+e1c+e1d+emb2) @ fc_w^T + fc_b + residual
    fc_kernel<<<dim3(4, NROWS / 64), 256>>>(fc_w, fc_b, h, out);
}

// round 14
// speedup vs baseline: 1.0828x; 1.0828x over previous
#include <cuda_runtime.h>
#include <math.h>

#define B_SZ   2
#define L_SZ   1024
#define DM     256
#define H_SZ   8
#define DK     32
#define NROWS  (B_SZ * L_SZ)            // 2048
#define INV_SQRT_DK 0.17677669529663687f

// -------- scratch (__device__ globals; no allocation allowed) --------
__device__ float g_hn  [NROWS * DM];
__device__ float g_q   [NROWS * DM];
__device__ float g_k   [NROWS * DM];
__device__ float g_v   [NROWS * DM];
__device__ float g_emb [NROWS * DM];
__device__ float g_emb3[NROWS * DM];
__device__ float g_emb2[NROWS * DM];
__device__ float g_il  [H_SZ * NROWS];   // per (h,b,i) 1/l

// -------- f32x2 packed helpers --------
__device__ __forceinline__ unsigned long long pk2(float a, float b) {
    unsigned long long r;
    asm("mov.b64 %0, {%1, %2};" : "=l"(r) : "f"(a), "f"(b));
    return r;
}
__device__ __forceinline__ void upk2(unsigned long long v, float& a, float& b) {
    asm("mov.b64 {%0, %1}, %2;" : "=f"(a), "=f"(b) : "l"(v));
}
__device__ __forceinline__ unsigned long long ffma2(unsigned long long a,
                                                    unsigned long long b,
                                                    unsigned long long c) {
    unsigned long long d;
    asm("fma.rn.f32x2 %0, %1, %2, %3;" : "=l"(d) : "l"(a), "l"(b), "l"(c));
    return d;
}

// -------- L2 cache-policy helpers (cache_hint form) --------
__device__ __forceinline__ unsigned long long policy_evict_last() {
    unsigned long long pol;
    asm("createpolicy.fractional.L2::evict_last.b64 %0, 1.0;" : "=l"(pol));
    return pol;
}
__device__ __forceinline__ unsigned long long policy_evict_first() {
    unsigned long long pol;
    asm("createpolicy.fractional.L2::evict_first.b64 %0, 1.0;" : "=l"(pol));
    return pol;
}
__device__ __forceinline__ float4 ldg_hint4(const float* p, unsigned long long pol) {
    float4 v;
    asm volatile("ld.global.nc.L2::cache_hint.v4.f32 {%0,%1,%2,%3}, [%4], %5;"
        : "=f"(v.x), "=f"(v.y), "=f"(v.z), "=f"(v.w) : "l"(p), "l"(pol));
    return v;
}
__device__ __forceinline__ void stg_hint(float* p, float v, unsigned long long pol) {
    asm volatile("st.global.L2::cache_hint.f32 [%0], %1, %2;"
        :: "l"(p), "f"(v), "l"(pol) : "memory");
}
__device__ __forceinline__ void stg_hint4(float* p, float4 v, unsigned long long pol) {
    asm volatile("st.global.L2::cache_hint.v4.f32 [%0], {%1,%2,%3,%4}, %5;"
        :: "l"(p), "f"(v.x), "f"(v.y), "f"(v.z), "f"(v.w), "l"(pol) : "memory");
}

// ---------------------------------------------------------------
// LayerNorm
// ---------------------------------------------------------------
__global__ void ln_kernel(const float* __restrict__ hin,
                          const float* __restrict__ gam,
                          const float* __restrict__ bta)
{
    int row = blockIdx.x, tid = threadIdx.x;
    float x = hin[(size_t)row * DM + tid];
    float s1 = x, s2 = x * x;
    #pragma unroll
    for (int o = 16; o; o >>= 1) {
        s1 += __shfl_xor_sync(0xffffffffu, s1, o);
        s2 += __shfl_xor_sync(0xffffffffu, s2, o);
    }
    __shared__ float r1[8], r2[8];
    __shared__ float mu_s, rstd_s;
    if ((tid & 31) == 0) { r1[tid >> 5] = s1; r2[tid >> 5] = s2; }
    __syncthreads();
    if (tid == 0) {
        float a = 0.f, c = 0.f;
        #pragma unroll
        for (int i = 0; i < 8; i++) { a += r1[i]; c += r2[i]; }
        float mu  = a * (1.0f / DM);
        float var = c * (1.0f / DM) - mu * mu;
        mu_s = mu; rstd_s = rsqrtf(var + 1e-5f);
    }
    __syncthreads();
    g_hn[(size_t)row * DM + tid] = (x - mu_s) * rstd_s * gam[tid] + bta[tid];
}

// ---------------------------------------------------------------
// Fused QKV projection, f32x2, double-buffered k-loop. grid (12, 32)
// ---------------------------------------------------------------
__global__ void qkv_kernel(const float* __restrict__ w_qs,
                           const float* __restrict__ w_ks,
                           const float* __restrict__ w_vs)
{
    __shared__ float As[2][16][64];
    __shared__ float Bs[2][16][64];
    int tid = threadIdx.x;
    int sel = blockIdx.x >> 2;
    int n0  = (blockIdx.x & 3) * 64;
    int m0  = blockIdx.y * 64;
    const float* Bm = (sel == 0) ? w_qs : (sel == 1) ? w_ks : w_vs;
    float* C = (sel == 0) ? g_q : (sel == 1) ? g_k : g_v;
    float scale = (sel == 0) ? INV_SQRT_DK : 1.0f;

    int tx = tid & 15, ty = tid >> 4;
    int lr = tid >> 2, lc = (tid & 3) * 4;
    unsigned long long acc[4][2];
    #pragma unroll
    for (int i = 0; i < 4; i++) { acc[i][0] = 0ull; acc[i][1] = 0ull; }

    const float* Aptr = g_hn + (size_t)(m0 + lr) * DM + lc;
    const float* Bptr = Bm   + (size_t)(n0 + lr) * DM + lc;

    {
        float4 av = *(const float4*)Aptr;
        float4 bv = *(const float4*)Bptr;
        As[0][lc + 0][lr] = av.x; As[0][lc + 1][lr] = av.y; As[0][lc + 2][lr] = av.z; As[0][lc + 3][lr] = av.w;
        Bs[0][lc + 0][lr] = bv.x; Bs[0][lc + 1][lr] = bv.y; Bs[0][lc + 2][lr] = bv.z; Bs[0][lc + 3][lr] = bv.w;
    }
    __syncthreads();

    for (int t = 0; t < 16; t++) {
        int cur = t & 1;
        float4 av2, bv2;
        if (t < 15) {
            av2 = *(const float4*)(Aptr + (t + 1) * 16);
            bv2 = *(const float4*)(Bptr + (t + 1) * 16);
        }
        #pragma unroll
        for (int kk = 0; kk < 16; kk++) {
            float4 a = *(const float4*)&As[cur][kk][ty * 4];
            ulonglong2 b2 = *(const ulonglong2*)&Bs[cur][kk][tx * 4];
            unsigned long long ap;
            ap = pk2(a.x, a.x);
            acc[0][0] = ffma2(b2.x, ap, acc[0][0]);
            acc[0][1] = ffma2(b2.y, ap, acc[0][1]);
            ap = pk2(a.y, a.y);
            acc[1][0] = ffma2(b2.x, ap, acc[1][0]);
            acc[1][1] = ffma2(b2.y, ap, acc[1][1]);
            ap = pk2(a.z, a.z);
            acc[2][0] = ffma2(b2.x, ap, acc[2][0]);
            acc[2][1] = ffma2(b2.y, ap, acc[2][1]);
            ap = pk2(a.w, a.w);
            acc[3][0] = ffma2(b2.x, ap, acc[3][0]);
            acc[3][1] = ffma2(b2.y, ap, acc[3][1]);
        }
        if (t < 15) {
            int nx = cur ^ 1;
            As[nx][lc + 0][lr] = av2.x; As[nx][lc + 1][lr] = av2.y; As[nx][lc + 2][lr] = av2.z; As[nx][lc + 3][lr] = av2.w;
            Bs[nx][lc + 0][lr] = bv2.x; Bs[nx][lc + 1][lr] = bv2.y; Bs[nx][lc + 2][lr] = bv2.z; Bs[nx][lc + 3][lr] = bv2.w;
        }
        __syncthreads();
    }
    #pragma unroll
    for (int i = 0; i < 4; i++) {
        int m = m0 + ty * 4 + i;
        float r0, r1, r2, r3;
        upk2(acc[i][0], r0, r1);
        upk2(acc[i][1], r2, r3);
        float4 o = make_float4(r0 * scale, r1 * scale, r2 * scale, r3 * scale);
        *(float4*)(C + (size_t)m * DM + n0 + tx * 4) = o;
    }
}

// ---------------------------------------------------------------
// s1: raw attn1 = qhat . k, f32x2. 64x64 tiles. grid (16,16,16)
// attn1 stored evict_last so the tail is L2-resident when s2 starts.
// ---------------------------------------------------------------
__global__ void s1_kernel(float* __restrict__ attn)
{
    __shared__ float Qs[32][64];
    __shared__ float Ks[32][64];
    int tid = threadIdx.x;
    int bh = blockIdx.z; int b = bh & 1; int h = bh >> 1;
    int i0 = blockIdx.y * 64, j0 = blockIdx.x * 64;
    const unsigned long long POL_EL = policy_evict_last();

    {
        int r  = tid >> 2;
        int c4 = (tid & 3) * 8;
        const float* qp = g_q + ((size_t)(b * L_SZ) + i0 + r) * DM + h * DK + c4;
        const float* kp = g_k + ((size_t)(b * L_SZ) + j0 + r) * DM + h * DK + c4;
        float4 a0 = *(const float4*)qp, a1 = *(const float4*)(qp + 4);
        float4 c0 = *(const float4*)kp, c1 = *(const float4*)(kp + 4);
        Qs[c4 + 0][r] = a0.x; Qs[c4 + 1][r] = a0.y; Qs[c4 + 2][r] = a0.z; Qs[c4 + 3][r] = a0.w;
        Qs[c4 + 4][r] = a1.x; Qs[c4 + 5][r] = a1.y; Qs[c4 + 6][r] = a1.z; Qs[c4 + 7][r] = a1.w;
        Ks[c4 + 0][r] = c0.x; Ks[c4 + 1][r] = c0.y; Ks[c4 + 2][r] = c0.z; Ks[c4 + 3][r] = c0.w;
        Ks[c4 + 4][r] = c1.x; Ks[c4 + 5][r] = c1.y; Ks[c4 + 6][r] = c1.z; Ks[c4 + 7][r] = c1.w;
    }
    __syncthreads();

    int tx = tid & 15, ty = tid >> 4;
    unsigned long long acc[4][2];
    #pragma unroll
    for (int i = 0; i < 4; i++) { acc[i][0] = 0ull; acc[i][1] = 0ull; }

    #pragma unroll
    for (int kk = 0; kk < 32; kk++) {
        float4 a = *(const float4*)&Qs[kk][ty * 4];
        ulonglong2 c2 = *(const ulonglong2*)&Ks[kk][tx * 4];
        unsigned long long ap;
        ap = pk2(a.x, a.x);
        acc[0][0] = ffma2(c2.x, ap, acc[0][0]);
        acc[0][1] = ffma2(c2.y, ap, acc[0][1]);
        ap = pk2(a.y, a.y);
        acc[1][0] = ffma2(c2.x, ap, acc[1][0]);
        acc[1][1] = ffma2(c2.y, ap, acc[1][1]);
        ap = pk2(a.z, a.z);
        acc[2][0] = ffma2(c2.x, ap, acc[2][0]);
        acc[2][1] = ffma2(c2.y, ap, acc[2][1]);
        ap = pk2(a.w, a.w);
        acc[3][0] = ffma2(c2.x, ap, acc[3][0]);
        acc[3][1] = ffma2(c2.y, ap, acc[3][1]);
    }
    #pragma unroll
    for (int ii = 0; ii < 4; ii++) {
        int i = i0 + ty * 4 + ii;
        float4 r;
        upk2(acc[ii][0], r.x, r.y);
        upk2(acc[ii][1], r.z, r.w);
        stg_hint4(attn + ((size_t)((h * B_SZ + b) * L_SZ + i)) * L_SZ + j0 + tx * 4, r, POL_EL);
    }
}

// ---------------------------------------------------------------
// s2 fused: 128-thread CTAs, full grid (1024). attn1 LDGs hoisted;
// bias evict_first; p evict_last.
// ---------------------------------------------------------------
#define BT_STRIDE 33
#define PS_STRIDE 12
__global__ void __launch_bounds__(128) s2_kernel(const float* __restrict__ bias,
                                                 float* __restrict__ attn)
{
    extern __shared__ float sm4[];
    float* qp = sm4;                          // 512
    float* bt = sm4 + 512;                    // 4224
    float* ps = sm4 + 512 + 4224;             // 1536
    float* cl = sm4 + 512 + 4224 + 1536;      // 32
    float* co = cl + 32;                      // 512

    int tid = threadIdx.x;
    int w = tid >> 5, lane = tid & 31;
    int r0 = blockIdx.x * 2;
    const unsigned long long POL_EL = policy_evict_last();
    const unsigned long long POL_EF = policy_evict_first();

    for (int e = tid; e < 512; e += 128) {
        int row = e >> 8, x = e & 255, h = x >> 5, d = x & 31;
        qp[row * 256 + d * 8 + h] = g_q[(size_t)(r0 + row) * DM + x];
    }
    __syncthreads();

    int rl   = w >> 1;
    int half = w & 1;
    int r    = r0 + rl;

    const float* qprow = qp + rl * 256;
    float* btw = bt + w * (32 * BT_STRIDE);
    float* psw = ps + w * (32 * PS_STRIDE);

    const float* bsrc = bias + (size_t)r * L_SZ * DK;
    float* arow = attn + ((size_t)r << 10);

    unsigned long long lpk[4], o2pk[4];
    #pragma unroll
    for (int k = 0; k < 4; k++) { lpk[k] = 0ull; o2pk[k] = 0ull; }
    const unsigned long long ONE2 = pk2(1.0f, 1.0f);

    for (int jt = 0; jt < 16; jt++) {
        int j0 = half * 512 + jt * 32;

        // ---- hoisted attn1 loads (overlap with bias staging) ----
        float s0 = arow[(0ull << 21) + j0 + lane];
        float s1 = arow[(1ull << 21) + j0 + lane];
        float s2v = arow[(2ull << 21) + j0 + lane];
        float s3 = arow[(3ull << 21) + j0 + lane];
        float s4 = arow[(4ull << 21) + j0 + lane];
        float s5 = arow[(5ull << 21) + j0 + lane];
        float s6 = arow[(6ull << 21) + j0 + lane];
        float s7 = arow[(7ull << 21) + j0 + lane];

        // ---- stage bias tile transposed: bt[d][j] ----
        #pragma unroll
        for (int it = 0; it < 8; it++) {
            int e  = it * 32 + lane;
            int jj = e >> 3;
            int c8 = e & 7;
            float4 v = ldg_hint4(bsrc + ((size_t)(j0 + jj) * 8 + c8) * 4, POL_EF);
            btw[(c8 * 4 + 0) * BT_STRIDE + jj] = v.x;
            btw[(c8 * 4 + 1) * BT_STRIDE + jj] = v.y;
            btw[(c8 * 4 + 2) * BT_STRIDE + jj] = v.z;
            btw[(c8 * 4 + 3) * BT_STRIDE + jj] = v.w;
        }
        __syncwarp();

        unsigned long long spk[4];
        spk[0] = pk2(s0, s1); spk[1] = pk2(s2v, s3);
        spk[2] = pk2(s4, s5); spk[3] = pk2(s6, s7);

        #pragma unroll
        for (int d = 0; d < 32; d++) {
            float bb = btw[d * BT_STRIDE + lane];
            unsigned long long bbp = pk2(bb, bb);
            ulonglong2 qA = *(const ulonglong2*)(qprow + d * 8);
            ulonglong2 qB = *(const ulonglong2*)(qprow + d * 8 + 4);
            spk[0] = ffma2(qA.x, bbp, spk[0]);
            spk[1] = ffma2(qA.y, bbp, spk[1]);
            spk[2] = ffma2(qB.x, bbp, spk[2]);
            spk[3] = ffma2(qB.y, bbp, spk[3]);
        }

        float p[8];
        {
            float a, b2;
            #pragma unroll
            for (int k = 0; k < 4; k++) {
                upk2(spk[k], a, b2);
                p[2 * k]     = __expf(a);
                p[2 * k + 1] = __expf(b2);
            }
            float4* pd = (float4*)(psw + lane * PS_STRIDE);
            pd[0] = make_float4(p[0], p[1], p[2], p[3]);
            pd[1] = make_float4(p[4], p[5], p[6], p[7]);
            #pragma unroll
            for (int h = 0; h < 8; h++)
                stg_hint(arow + ((unsigned long long)h << 21) + j0 + lane, p[h], POL_EL);
            #pragma unroll
            for (int k = 0; k < 4; k++)
                lpk[k] = ffma2(pk2(p[2 * k], p[2 * k + 1]), ONE2, lpk[k]);
        }
        __syncwarp();

        #pragma unroll 4
        for (int j = 0; j < 32; j++) {
            float bb = btw[lane * BT_STRIDE + j];
            unsigned long long bbp = pk2(bb, bb);
            ulonglong2 pv0 = *(const ulonglong2*)(psw + j * PS_STRIDE);
            ulonglong2 pv1 = *(const ulonglong2*)(psw + j * PS_STRIDE + 4);
            o2pk[0] = ffma2(pv0.x, bbp, o2pk[0]);
            o2pk[1] = ffma2(pv0.y, bbp, o2pk[1]);
            o2pk[2] = ffma2(pv1.x, bbp, o2pk[2]);
            o2pk[3] = ffma2(pv1.y, bbp, o2pk[3]);
        }
        __syncwarp();
    }

    float l[8], o2[8];
    #pragma unroll
    for (int k = 0; k < 4; k++) {
        upk2(lpk[k],  l[2 * k],  l[2 * k + 1]);
        upk2(o2pk[k], o2[2 * k], o2[2 * k + 1]);
    }
    #pragma unroll
    for (int h = 0; h < 8; h++) {
        float ls = l[h];
        #pragma unroll
        for (int o = 16; o; o >>= 1)
            ls += __shfl_xor_sync(0xffffffffu, ls, o);
        l[h] = ls;
    }

    if (lane == 0) {
        #pragma unroll
        for (int h = 0; h < 8; h++) cl[(rl * 2 + half) * 8 + h] = l[h];
    }
    if (half == 1) {
        #pragma unroll
        for (int h = 0; h < 8; h++) co[(rl * 8 + h) * 32 + lane] = o2[h];
    }
    __syncthreads();
    if (half == 0) {
        #pragma unroll
        for (int h = 0; h < 8; h++) {
            float ltot = cl[(rl * 2) * 8 + h] + cl[(rl * 2 + 1) * 8 + h];
            float invl = 1.0f / ltot;
            float ot = o2[h] + co[(rl * 8 + h) * 32 + lane];
            g_emb2[(size_t)r * DM + h * DK + lane] = ot * invl;
            if (lane == 0)
                g_il[h * NROWS + r] = invl;
        }
    }
}

// ---------------------------------------------------------------
// e1: double-buffered pipeline over a 512-j half. Normalizes attn
// in place (evict_first). grid (16, 16, 2).
// ---------------------------------------------------------------
__global__ void e1_kernel(float* __restrict__ attn)
{
    __shared__ float At[2][32][65];
    __shared__ float Vs[2][32][36];
    int tid = threadIdx.x;
    int bh = blockIdx.y; int b = bh & 1; int h = bh >> 1;
    int i0 = blockIdx.x * 64;
    int jh = blockIdx.z;
    float* eout = jh ? g_emb3 : g_emb;
    int w = tid >> 5, lane = tid & 31;
    const unsigned long long POL_EF = policy_evict_first();

    int rr = tid >> 3;
    int jc = (tid & 7) * 4;
    float invl0 = g_il[h * NROWS + b * L_SZ + i0 + rr];
    float invl1 = g_il[h * NROWS + b * L_SZ + i0 + rr + 32];

    float* a0base = attn + ((size_t)((h * B_SZ + b) * L_SZ + i0 + rr)) * L_SZ + jh * 512 + jc;
    float* a1base = a0base + (size_t)32 * L_SZ;
    const float* vbase = g_v + ((size_t)(b * L_SZ) + jh * 512 + rr) * DM + h * DK + jc;

    unsigned long long acc[2][2];
    acc[0][0] = 0ull; acc[0][1] = 0ull; acc[1][0] = 0ull; acc[1][1] = 0ull;

    float4 a0r, a1r, vr;
    {
        float4 a = *(float4*)a0base;
        a.x *= invl0; a.y *= invl0; a.z *= invl0; a.w *= invl0;
        stg_hint4(a0base, a, POL_EF); a0r = a;
        float4 c = *(float4*)a1base;
        c.x *= invl1; c.y *= invl1; c.z *= invl1; c.w *= invl1;
        stg_hint4(a1base, c, POL_EF); a1r = c;
        vr = __ldg((const float4*)vbase);
    }
    At[0][jc + 0][rr] = a0r.x; At[0][jc + 1][rr] = a0r.y;
    At[0][jc + 2][rr] = a0r.z; At[0][jc + 3][rr] = a0r.w;
    At[0][jc + 0][rr + 32] = a1r.x; At[0][jc + 1][rr + 32] = a1r.y;
    At[0][jc + 2][rr + 32] = a1r.z; At[0][jc + 3][rr + 32] = a1r.w;
    *(float4*)&Vs[0][rr][jc] = vr;
    __syncthreads();

    for (int jt = 0; jt < 16; jt++) {
        int cur = jt & 1;
        if (jt < 15) {
            int off = (jt + 1) * 32;
            float4 a = *(float4*)(a0base + off);
            a.x *= invl0; a.y *= invl0; a.z *= invl0; a.w *= invl0;
            stg_hint4(a0base + off, a, POL_EF); a0r = a;
            float4 c = *(float4*)(a1base + off);
            c.x *= invl1; c.y *= invl1; c.z *= invl1; c.w *= invl1;
            stg_hint4(a1base + off, c, POL_EF); a1r = c;
            vr = __ldg((const float4*)(vbase + (size_t)off * DM));
        }
        #pragma unroll
        for (int kk = 0; kk < 32; kk++) {
            ulonglong2 v2 = *(const ulonglong2*)&Vs[cur][kk][w * 4];
            float a0 = At[cur][kk][lane];
            float a1 = At[cur][kk][lane + 32];
            unsigned long long ap0 = pk2(a0, a0);
            unsigned long long ap1 = pk2(a1, a1);
            acc[0][0] = ffma2(v2.x, ap0, acc[0][0]);
            acc[0][1] = ffma2(v2.y, ap0, acc[0][1]);
            acc[1][0] = ffma2(v2.x, ap1, acc[1][0]);
            acc[1][1] = ffma2(v2.y, ap1, acc[1][1]);
        }
        if (jt < 15) {
            int nx = cur ^ 1;
            At[nx][jc + 0][rr] = a0r.x; At[nx][jc + 1][rr] = a0r.y;
            At[nx][jc + 2][rr] = a0r.z; At[nx][jc + 3][rr] = a0r.w;
            At[nx][jc + 0][rr + 32] = a1r.x; At[nx][jc + 1][rr + 32] = a1r.y;
            At[nx][jc + 2][rr + 32] = a1r.z; At[nx][jc + 3][rr + 32] = a1r.w;
            *(float4*)&Vs[nx][rr][jc] = vr;
        }
        __syncthreads();
    }
    #pragma unroll
    for (int p = 0; p < 2; p++) {
        float4 o;
        upk2(acc[p][0], o.x, o.y);
        upk2(acc[p][1], o.z, o.w);
        *(float4*)(eout + ((size_t)(b * L_SZ) + i0 + lane + p * 32) * DM + h * DK + w * 4) = o;
    }
}

// ---------------------------------------------------------------
// fc: out = (emb1a+emb1b+emb2) @ fc_w^T + fc_b + residual, f32x2,
// double-buffered k-loop. grid (4, 32)
// ---------------------------------------------------------------
__global__ void fc_kernel(const float* __restrict__ Bm,
                          const float* __restrict__ fcb,
                          const float* __restrict__ res,
                          float* __restrict__ C)
{
    __shared__ float As[2][16][64];
    __shared__ float Bs[2][16][64];
    int tid = threadIdx.x;
    int tx = tid & 15, ty = tid >> 4;
    int m0 = blockIdx.y * 64, n0 = blockIdx.x * 64;
    int lr = tid >> 2, lc = (tid & 3) * 4;
    unsigned long long acc[4][2];
    #pragma unroll
    for (int i = 0; i < 4; i++) { acc[i][0] = 0ull; acc[i][1] = 0ull; }

    size_t abase = (size_t)(m0 + lr) * DM + lc;
    const float* Bptr = Bm + (size_t)(n0 + lr) * DM + lc;

    {
        float4 a1 = *(const float4*)(g_emb  + abase);
        float4 a3 = *(const float4*)(g_emb3 + abase);
        float4 a2 = *(const float4*)(g_emb2 + abase);
        float4 bv = *(const float4*)Bptr;
        As[0][lc + 0][lr] = a1.x + a3.x + a2.x; As[0][lc + 1][lr] = a1.y + a3.y + a2.y;
        As[0][lc + 2][lr] = a1.z + a3.z + a2.z; As[0][lc + 3][lr] = a1.w + a3.w + a2.w;
        Bs[0][lc + 0][lr] = bv.x; Bs[0][lc + 1][lr] = bv.y; Bs[0][lc + 2][lr] = bv.z; Bs[0][lc + 3][lr] = bv.w;
    }
    __syncthreads();

    for (int t = 0; t < 16; t++) {
        int cur = t & 1;
        float4 asum, bv2;
        if (t < 15) {
            size_t aoff = abase + (t + 1) * 16;
            float4 a1 = *(const float4*)(g_emb  + aoff);
            float4 a3 = *(const float4*)(g_emb3 + aoff);
            float4 a2 = *(const float4*)(g_emb2 + aoff);
            asum.x = a1.x + a3.x + a2.x; asum.y = a1.y + a3.y + a2.y;
            asum.z = a1.z + a3.z + a2.z; asum.w = a1.w + a3.w + a2.w;
            bv2 = *(const float4*)(Bptr + (t + 1) * 16);
        }
        #pragma unroll
        for (int kk = 0; kk < 16; kk++) {
            float4 a = *(const float4*)&As[cur][kk][ty * 4];
            ulonglong2 b2 = *(const ulonglong2*)&Bs[cur][kk][tx * 4];
            unsigned long long ap;
            ap = pk2(a.x, a.x);
            acc[0][0] = ffma2(b2.x, ap, acc[0][0]);
            acc[0][1] = ffma2(b2.y, ap, acc[0][1]);
            ap = pk2(a.y, a.y);
            acc[1][0] = ffma2(b2.x, ap, acc[1][0]);
            acc[1][1] = ffma2(b2.y, ap, acc[1][1]);
            ap = pk2(a.z, a.z);
            acc[2][0] = ffma2(b2.x, ap, acc[2][0]);
            acc[2][1] = ffma2(b2.y, ap, acc[2][1]);
            ap = pk2(a.w, a.w);
            acc[3][0] = ffma2(b2.x, ap, acc[3][0]);
            acc[3][1] = ffma2(b2.y, ap, acc[3][1]);
        }
        if (t < 15) {
            int nx = cur ^ 1;
            As[nx][lc + 0][lr] = asum.x; As[nx][lc + 1][lr] = asum.y;
            As[nx][lc + 2][lr] = asum.z; As[nx][lc + 3][lr] = asum.w;
            Bs[nx][lc + 0][lr] = bv2.x; Bs[nx][lc + 1][lr] = bv2.y;
            Bs[nx][lc + 2][lr] = bv2.z; Bs[nx][lc + 3][lr] = bv2.w;
        }
        __syncthreads();
    }
    #pragma unroll
    for (int i = 0; i < 4; i++) {
        int m = m0 + ty * 4 + i;
        float r0, r1, r2, r3;
        upk2(acc[i][0], r0, r1);
        upk2(acc[i][1], r2, r3);
        int n = n0 + tx * 4;
        const float4 rv = *(const float4*)(res + (size_t)m * DM + n);
        const float4 bb = *(const float4*)(fcb + n);
        float4 o;
        o.x = r0 + bb.x + rv.x;
        o.y = r1 + bb.y + rv.y;
        o.z = r2 + bb.z + rv.z;
        o.w = r3 + bb.w + rv.w;
        *(float4*)(C + (size_t)m * DM + n) = o;
    }
}

// ---------------------------------------------------------------
extern "C" void kernel_launch(void* const* d_in, const int* in_sizes, int n_in,
                              void* d_out, int out_size)
{
    const float* h    = (const float*)d_in[0];
    const float* bias = (const float*)d_in[1];
    const float* w_qs = (const float*)d_in[2];
    const float* w_ks = (const float*)d_in[3];
    const float* w_vs = (const float*)d_in[4];
    const float* ln_g = (const float*)d_in[5];
    const float* ln_b = (const float*)d_in[6];
    const float* fc_w = (const float*)d_in[7];
    const float* fc_b = (const float*)d_in[8];

    float* out  = (float*)d_out;                       // (B, L, 256)
    float* attn = out + (size_t)B_SZ * L_SZ * DM;      // (H, B, L, L)

    const int SMEM_S2 = (512 + 4224 + 1536 + 32 + 512) * sizeof(float);  // 27264 B
    cudaFuncSetAttribute(s2_kernel, cudaFuncAttributeMaxDynamicSharedMemorySize, SMEM_S2);

    // 1. LayerNorm
    ln_kernel<<<NROWS, 256>>>(h, ln_g, ln_b);

    // 2. QKV projections (q pre-scaled), double-buffered
    qkv_kernel<<<dim3(12, NROWS / 64), 256>>>(w_qs, w_ks, w_vs);

    // 3. attn1 raw scores (evict_last stores)
    s1_kernel<<<dim3(16, 16, 16), 256>>>(attn);

    // 4. fused s2 (full grid, hoisted loads, L2 policies)
    s2_kernel<<<NROWS / 2, 128, SMEM_S2>>>(bias, attn);

    // 5. emb1 halves = attn @ v, pipelined, normalizing attn in place
    e1_kernel<<<dim3(16, 16, 2), 256>>>(attn);

    // 6. out = (emb1a+emb1b+emb2) @ fc_w^T + fc_b + residual
    fc_kernel<<<dim3(4, NROWS / 64), 256>>>(fc_w, fc_b, h, out);
}

// round 16
// speedup vs baseline: 1.0931x; 1.0096x over previous
#include <cuda_runtime.h>
#include <math.h>

#define B_SZ   2
#define L_SZ   1024
#define DM     256
#define H_SZ   8
#define DK     32
#define NROWS  (B_SZ * L_SZ)            // 2048
#define INV_SQRT_DK 0.17677669529663687f

// -------- scratch (__device__ globals; no allocation allowed) --------
__device__ float g_hn  [NROWS * DM];
__device__ float g_q   [NROWS * DM];
__device__ float g_k   [NROWS * DM];
__device__ float g_v   [NROWS * DM];
__device__ float g_e1a [NROWS * DM];
__device__ float g_e1b [NROWS * DM];
__device__ float g_e1c [NROWS * DM];
__device__ float g_e1d [NROWS * DM];
__device__ float g_emb2[NROWS * DM];
__device__ float g_il  [H_SZ * NROWS];   // per (h,b,i) 1/l

// -------- f32x2 packed helpers --------
__device__ __forceinline__ unsigned long long pk2(float a, float b) {
    unsigned long long r;
    asm("mov.b64 %0, {%1, %2};" : "=l"(r) : "f"(a), "f"(b));
    return r;
}
__device__ __forceinline__ void upk2(unsigned long long v, float& a, float& b) {
    asm("mov.b64 {%0, %1}, %2;" : "=f"(a), "=f"(b) : "l"(v));
}
__device__ __forceinline__ unsigned long long ffma2(unsigned long long a,
                                                    unsigned long long b,
                                                    unsigned long long c) {
    unsigned long long d;
    asm("fma.rn.f32x2 %0, %1, %2, %3;" : "=l"(d) : "l"(a), "l"(b), "l"(c));
    return d;
}

// -------- L2 cache-policy helpers (cache_hint form) --------
__device__ __forceinline__ unsigned long long policy_evict_last() {
    unsigned long long pol;
    asm("createpolicy.fractional.L2::evict_last.b64 %0, 1.0;" : "=l"(pol));
    return pol;
}
__device__ __forceinline__ unsigned long long policy_evict_first() {
    unsigned long long pol;
    asm("createpolicy.fractional.L2::evict_first.b64 %0, 1.0;" : "=l"(pol));
    return pol;
}
__device__ __forceinline__ float4 ldg_hint4(const float* p, unsigned long long pol) {
    float4 v;
    asm volatile("ld.global.nc.L2::cache_hint.v4.f32 {%0,%1,%2,%3}, [%4], %5;"
        : "=f"(v.x), "=f"(v.y), "=f"(v.z), "=f"(v.w) : "l"(p), "l"(pol));
    return v;
}
__device__ __forceinline__ void stg_hint(float* p, float v, unsigned long long pol) {
    asm volatile("st.global.L2::cache_hint.f32 [%0], %1, %2;"
        :: "l"(p), "f"(v), "l"(pol) : "memory");
}
__device__ __forceinline__ void stg_hint4(float* p, float4 v, unsigned long long pol) {
    asm volatile("st.global.L2::cache_hint.v4.f32 [%0], {%1,%2,%3,%4}, %5;"
        :: "l"(p), "f"(v.x), "f"(v.y), "f"(v.z), "f"(v.w), "l"(pol) : "memory");
}

// ---------------------------------------------------------------
// LayerNorm
// ---------------------------------------------------------------
__global__ void ln_kernel(const float* __restrict__ hin,
                          const float* __restrict__ gam,
                          const float* __restrict__ bta)
{
    int row = blockIdx.x, tid = threadIdx.x;
    float x = hin[(size_t)row * DM + tid];
    float s1 = x, s2 = x * x;
    #pragma unroll
    for (int o = 16; o; o >>= 1) {
        s1 += __shfl_xor_sync(0xffffffffu, s1, o);
        s2 += __shfl_xor_sync(0xffffffffu, s2, o);
    }
    __shared__ float r1[8], r2[8];
    __shared__ float mu_s, rstd_s;
    if ((tid & 31) == 0) { r1[tid >> 5] = s1; r2[tid >> 5] = s2; }
    __syncthreads();
    if (tid == 0) {
        float a = 0.f, c = 0.f;
        #pragma unroll
        for (int i = 0; i < 8; i++) { a += r1[i]; c += r2[i]; }
        float mu  = a * (1.0f / DM);
        float var = c * (1.0f / DM) - mu * mu;
        mu_s = mu; rstd_s = rsqrtf(var + 1e-5f);
    }
    __syncthreads();
    g_hn[(size_t)row * DM + tid] = (x - mu_s) * rstd_s * gam[tid] + bta[tid];
}

// ---------------------------------------------------------------
// Fused QKV projection, f32x2, double-buffered k-loop. grid (12, 32)
// ---------------------------------------------------------------
__global__ void qkv_kernel(const float* __restrict__ w_qs,
                           const float* __restrict__ w_ks,
                           const float* __restrict__ w_vs)
{
    __shared__ float As[2][16][64];
    __shared__ float Bs[2][16][64];
    int tid = threadIdx.x;
    int sel = blockIdx.x >> 2;
    int n0  = (blockIdx.x & 3) * 64;
    int m0  = blockIdx.y * 64;
    const float* Bm = (sel == 0) ? w_qs : (sel == 1) ? w_ks : w_vs;
    float* C = (sel == 0) ? g_q : (sel == 1) ? g_k : g_v;
    float scale = (sel == 0) ? INV_SQRT_DK : 1.0f;

    int tx = tid & 15, ty = tid >> 4;
    int lr = tid >> 2, lc = (tid & 3) * 4;
    unsigned long long acc[4][2];
    #pragma unroll
    for (int i = 0; i < 4; i++) { acc[i][0] = 0ull; acc[i][1] = 0ull; }

    const float* Aptr = g_hn + (size_t)(m0 + lr) * DM + lc;
    const float* Bptr = Bm   + (size_t)(n0 + lr) * DM + lc;

    {
        float4 av = *(const float4*)Aptr;
        float4 bv = *(const float4*)Bptr;
        As[0][lc + 0][lr] = av.x; As[0][lc + 1][lr] = av.y; As[0][lc + 2][lr] = av.z; As[0][lc + 3][lr] = av.w;
        Bs[0][lc + 0][lr] = bv.x; Bs[0][lc + 1][lr] = bv.y; Bs[0][lc + 2][lr] = bv.z; Bs[0][lc + 3][lr] = bv.w;
    }
    __syncthreads();

    for (int t = 0; t < 16; t++) {
        int cur = t & 1;
        float4 av2, bv2;
        if (t < 15) {
            av2 = *(const float4*)(Aptr + (t + 1) * 16);
            bv2 = *(const float4*)(Bptr + (t + 1) * 16);
        }
        #pragma unroll
        for (int kk = 0; kk < 16; kk++) {
            float4 a = *(const float4*)&As[cur][kk][ty * 4];
            ulonglong2 b2 = *(const ulonglong2*)&Bs[cur][kk][tx * 4];
            unsigned long long ap;
            ap = pk2(a.x, a.x);
            acc[0][0] = ffma2(b2.x, ap, acc[0][0]);
            acc[0][1] = ffma2(b2.y, ap, acc[0][1]);
            ap = pk2(a.y, a.y);
            acc[1][0] = ffma2(b2.x, ap, acc[1][0]);
            acc[1][1] = ffma2(b2.y, ap, acc[1][1]);
            ap = pk2(a.z, a.z);
            acc[2][0] = ffma2(b2.x, ap, acc[2][0]);
            acc[2][1] = ffma2(b2.y, ap, acc[2][1]);
            ap = pk2(a.w, a.w);
            acc[3][0] = ffma2(b2.x, ap, acc[3][0]);
            acc[3][1] = ffma2(b2.y, ap, acc[3][1]);
        }
        if (t < 15) {
            int nx = cur ^ 1;
            As[nx][lc + 0][lr] = av2.x; As[nx][lc + 1][lr] = av2.y; As[nx][lc + 2][lr] = av2.z; As[nx][lc + 3][lr] = av2.w;
            Bs[nx][lc + 0][lr] = bv2.x; Bs[nx][lc + 1][lr] = bv2.y; Bs[nx][lc + 2][lr] = bv2.z; Bs[nx][lc + 3][lr] = bv2.w;
        }
        __syncthreads();
    }
    #pragma unroll
    for (int i = 0; i < 4; i++) {
        int m = m0 + ty * 4 + i;
        float r0, r1, r2, r3;
        upk2(acc[i][0], r0, r1);
        upk2(acc[i][1], r2, r3);
        float4 o = make_float4(r0 * scale, r1 * scale, r2 * scale, r3 * scale);
        *(float4*)(C + (size_t)m * DM + n0 + tx * 4) = o;
    }
}

// ---------------------------------------------------------------
// s1: raw attn1 = qhat . k, f32x2. 64x64 tiles. grid (16,16,16)
// attn1 stored evict_last.
// ---------------------------------------------------------------
__global__ void s1_kernel(float* __restrict__ attn)
{
    __shared__ float Qs[32][64];
    __shared__ float Ks[32][64];
    int tid = threadIdx.x;
    int bh = blockIdx.z; int b = bh & 1; int h = bh >> 1;
    int i0 = blockIdx.y * 64, j0 = blockIdx.x * 64;
    const unsigned long long POL_EL = policy_evict_last();

    {
        int r  = tid >> 2;
        int c4 = (tid & 3) * 8;
        const float* qp = g_q + ((size_t)(b * L_SZ) + i0 + r) * DM + h * DK + c4;
        const float* kp = g_k + ((size_t)(b * L_SZ) + j0 + r) * DM + h * DK + c4;
        float4 a0 = *(const float4*)qp, a1 = *(const float4*)(qp + 4);
        float4 c0 = *(const float4*)kp, c1 = *(const float4*)(kp + 4);
        Qs[c4 + 0][r] = a0.x; Qs[c4 + 1][r] = a0.y; Qs[c4 + 2][r] = a0.z; Qs[c4 + 3][r] = a0.w;
        Qs[c4 + 4][r] = a1.x; Qs[c4 + 5][r] = a1.y; Qs[c4 + 6][r] = a1.z; Qs[c4 + 7][r] = a1.w;
        Ks[c4 + 0][r] = c0.x; Ks[c4 + 1][r] = c0.y; Ks[c4 + 2][r] = c0.z; Ks[c4 + 3][r] = c0.w;
        Ks[c4 + 4][r] = c1.x; Ks[c4 + 5][r] = c1.y; Ks[c4 + 6][r] = c1.z; Ks[c4 + 7][r] = c1.w;
    }
    __syncthreads();

    int tx = tid & 15, ty = tid >> 4;
    unsigned long long acc[4][2];
    #pragma unroll
    for (int i = 0; i < 4; i++) { acc[i][0] = 0ull; acc[i][1] = 0ull; }

    #pragma unroll
    for (int kk = 0; kk < 32; kk++) {
        float4 a = *(const float4*)&Qs[kk][ty * 4];
        ulonglong2 c2 = *(const ulonglong2*)&Ks[kk][tx * 4];
        unsigned long long ap;
        ap = pk2(a.x, a.x);
        acc[0][0] = ffma2(c2.x, ap, acc[0][0]);
        acc[0][1] = ffma2(c2.y, ap, acc[0][1]);
        ap = pk2(a.y, a.y);
        acc[1][0] = ffma2(c2.x, ap, acc[1][0]);
        acc[1][1] = ffma2(c2.y, ap, acc[1][1]);
        ap = pk2(a.z, a.z);
        acc[2][0] = ffma2(c2.x, ap, acc[2][0]);
        acc[2][1] = ffma2(c2.y, ap, acc[2][1]);
        ap = pk2(a.w, a.w);
        acc[3][0] = ffma2(c2.x, ap, acc[3][0]);
        acc[3][1] = ffma2(c2.y, ap, acc[3][1]);
    }
    #pragma unroll
    for (int ii = 0; ii < 4; ii++) {
        int i = i0 + ty * 4 + ii;
        float4 r;
        upk2(acc[ii][0], r.x, r.y);
        upk2(acc[ii][1], r.z, r.w);
        stg_hint4(attn + ((size_t)((h * B_SZ + b) * L_SZ + i)) * L_SZ + j0 + tx * 4, r, POL_EL);
    }
}

// ---------------------------------------------------------------
// s2 fused: 128-thread CTAs, full grid (1024). Hoisted attn1 loads;
// bias evict_first; p evict_last. (R12/R14 proven config.)
// ---------------------------------------------------------------
#define BT_STRIDE 33
#define PS_STRIDE 12
__global__ void __launch_bounds__(128) s2_kernel(const float* __restrict__ bias,
                                                 float* __restrict__ attn)
{
    extern __shared__ float sm4[];
    float* qp = sm4;                          // 512
    float* bt = sm4 + 512;                    // 4224
    float* ps = sm4 + 512 + 4224;             // 1536
    float* cl = sm4 + 512 + 4224 + 1536;      // 32
    float* co = cl + 32;                      // 512

    int tid = threadIdx.x;
    int w = tid >> 5, lane = tid & 31;
    int r0 = blockIdx.x * 2;
    const unsigned long long POL_EL = policy_evict_last();
    const unsigned long long POL_EF = policy_evict_first();

    for (int e = tid; e < 512; e += 128) {
        int row = e >> 8, x = e & 255, h = x >> 5, d = x & 31;
        qp[row * 256 + d * 8 + h] = g_q[(size_t)(r0 + row) * DM + x];
    }
    __syncthreads();

    int rl   = w >> 1;
    int half = w & 1;
    int r    = r0 + rl;

    const float* qprow = qp + rl * 256;
    float* btw = bt + w * (32 * BT_STRIDE);
    float* psw = ps + w * (32 * PS_STRIDE);

    const float* bsrc = bias + (size_t)r * L_SZ * DK;
    float* arow = attn + ((size_t)r << 10);

    unsigned long long lpk[4], o2pk[4];
    #pragma unroll
    for (int k = 0; k < 4; k++) { lpk[k] = 0ull; o2pk[k] = 0ull; }
    const unsigned long long ONE2 = pk2(1.0f, 1.0f);

    for (int jt = 0; jt < 16; jt++) {
        int j0 = half * 512 + jt * 32;

        float s0 = arow[(0ull << 21) + j0 + lane];
        float s1 = arow[(1ull << 21) + j0 + lane];
        float s2v = arow[(2ull << 21) + j0 + lane];
        float s3 = arow[(3ull << 21) + j0 + lane];
        float s4 = arow[(4ull << 21) + j0 + lane];
        float s5 = arow[(5ull << 21) + j0 + lane];
        float s6 = arow[(6ull << 21) + j0 + lane];
        float s7 = arow[(7ull << 21) + j0 + lane];

        #pragma unroll
        for (int it = 0; it < 8; it++) {
            int e  = it * 32 + lane;
            int jj = e >> 3;
            int c8 = e & 7;
            float4 v = ldg_hint4(bsrc + ((size_t)(j0 + jj) * 8 + c8) * 4, POL_EF);
            btw[(c8 * 4 + 0) * BT_STRIDE + jj] = v.x;
            btw[(c8 * 4 + 1) * BT_STRIDE + jj] = v.y;
            btw[(c8 * 4 + 2) * BT_STRIDE + jj] = v.z;
            btw[(c8 * 4 + 3) * BT_STRIDE + jj] = v.w;
        }
        __syncwarp();

        unsigned long long spk[4];
        spk[0] = pk2(s0, s1); spk[1] = pk2(s2v, s3);
        spk[2] = pk2(s4, s5); spk[3] = pk2(s6, s7);

        #pragma unroll
        for (int d = 0; d < 32; d++) {
            float bb = btw[d * BT_STRIDE + lane];
            unsigned long long bbp = pk2(bb, bb);
            ulonglong2 qA = *(const ulonglong2*)(qprow + d * 8);
            ulonglong2 qB = *(const ulonglong2*)(qprow + d * 8 + 4);
            spk[0] = ffma2(qA.x, bbp, spk[0]);
            spk[1] = ffma2(qA.y, bbp, spk[1]);
            spk[2] = ffma2(qB.x, bbp, spk[2]);
            spk[3] = ffma2(qB.y, bbp, spk[3]);
        }

        float p[8];
        {
            float a, b2;
            #pragma unroll
            for (int k = 0; k < 4; k++) {
                upk2(spk[k], a, b2);
                p[2 * k]     = __expf(a);
                p[2 * k + 1] = __expf(b2);
            }
            float4* pd = (float4*)(psw + lane * PS_STRIDE);
            pd[0] = make_float4(p[0], p[1], p[2], p[3]);
            pd[1] = make_float4(p[4], p[5], p[6], p[7]);
            #pragma unroll
            for (int h = 0; h < 8; h++)
                stg_hint(arow + ((unsigned long long)h << 21) + j0 + lane, p[h], POL_EL);
            #pragma unroll
            for (int k = 0; k < 4; k++)
                lpk[k] = ffma2(pk2(p[2 * k], p[2 * k + 1]), ONE2, lpk[k]);
        }
        __syncwarp();

        #pragma unroll 4
        for (int j = 0; j < 32; j++) {
            float bb = btw[lane * BT_STRIDE + j];
            unsigned long long bbp = pk2(bb, bb);
            ulonglong2 pv0 = *(const ulonglong2*)(psw + j * PS_STRIDE);
            ulonglong2 pv1 = *(const ulonglong2*)(psw + j * PS_STRIDE + 4);
            o2pk[0] = ffma2(pv0.x, bbp, o2pk[0]);
            o2pk[1] = ffma2(pv0.y, bbp, o2pk[1]);
            o2pk[2] = ffma2(pv1.x, bbp, o2pk[2]);
            o2pk[3] = ffma2(pv1.y, bbp, o2pk[3]);
        }
        __syncwarp();
    }

    float l[8], o2[8];
    #pragma unroll
    for (int k = 0; k < 4; k++) {
        upk2(lpk[k],  l[2 * k],  l[2 * k + 1]);
        upk2(o2pk[k], o2[2 * k], o2[2 * k + 1]);
    }
    #pragma unroll
    for (int h = 0; h < 8; h++) {
        float ls = l[h];
        #pragma unroll
        for (int o = 16; o; o >>= 1)
            ls += __shfl_xor_sync(0xffffffffu, ls, o);
        l[h] = ls;
    }

    if (lane == 0) {
        #pragma unroll
        for (int h = 0; h < 8; h++) cl[(rl * 2 + half) * 8 + h] = l[h];
    }
    if (half == 1) {
        #pragma unroll
        for (int h = 0; h < 8; h++) co[(rl * 8 + h) * 32 + lane] = o2[h];
    }
    __syncthreads();
    if (half == 0) {
        #pragma unroll
        for (int h = 0; h < 8; h++) {
            float ltot = cl[(rl * 2) * 8 + h] + cl[(rl * 2 + 1) * 8 + h];
            float invl = 1.0f / ltot;
            float ot = o2[h] + co[(rl * 8 + h) * 32 + lane];
            g_emb2[(size_t)r * DM + h * DK + lane] = ot * invl;
            if (lane == 0)
                g_il[h * NROWS + r] = invl;
        }
    }
}

// ---------------------------------------------------------------
// e1 v4: 2 heads per CTA, 8 d-cols per warp (smem wf ratio 0.5).
// grid (16 i-blk, 8 = b*4 head-pairs, 4 j-quarter), 256 thr.
// Normalizes attn in place (evict_first). Double-buffered.
// smem: At[2][2][32][65] | Vs[2][32][68]
// ---------------------------------------------------------------
#define AT_BUF  (2 * 32 * 65)          // per-buffer At floats (both hsel)
#define AT_H    (32 * 65)
#define VS_BUF  (32 * 68)
#define E1_SMEM ((2 * AT_BUF + 2 * VS_BUF) * sizeof(float))   // 50688 B
__global__ void __launch_bounds__(256) e1_kernel(float* __restrict__ attn)
{
    extern __shared__ float sm5[];
    float* Atb = sm5;                  // 2 * AT_BUF
    float* Vsb = sm5 + 2 * AT_BUF;     // 2 * VS_BUF

    int tid = threadIdx.x;
    int w = tid >> 5, lane = tid & 31;
    int i0 = blockIdx.x * 64;
    int b  = blockIdx.y & 1;
    int hp = blockIdx.y >> 1;          // 0..3 (head pair)
    int jq = blockIdx.z;
    float* eout = (jq == 0) ? g_e1a : (jq == 1) ? g_e1b : (jq == 2) ? g_e1c : g_e1d;
    const unsigned long long POL_EF = policy_evict_first();

    // compute mapping
    int s  = w >> 2;                   // h-sel within pair
    int w4 = w & 3;                    // d-octet
    int h  = hp * 2 + s;               // 0..7

    // staging mapping
    int hs = tid >> 7;                 // h group for staging
    int t  = tid & 127;
    int jc = (t & 7) * 4;              // j within 32-tile
    int rr = t >> 3;                   // 0..15 -> rows rr + 16k
    int hh = hp * 2 + hs;              // 0..7

    float invl[4];
    #pragma unroll
    for (int k = 0; k < 4; k++)
        invl[k] = g_il[hh * NROWS + b * L_SZ + i0 + rr + 16 * k];

    float* abase = attn + ((size_t)((hh * B_SZ + b) * L_SZ + i0 + rr)) * L_SZ + jq * 256 + jc;
    int vrow = tid >> 3;               // 0..31
    int vc   = (tid & 7) * 8;          // 0..56
    const float* vbase = g_v + ((size_t)(b * L_SZ) + jq * 256 + vrow) * DM + hp * 64 + vc;

    unsigned long long acc[2][4];
    #pragma unroll
    for (int p = 0; p < 2; p++)
        #pragma unroll
        for (int k = 0; k < 4; k++) acc[p][k] = 0ull;

    float4 ar[4], vr0, vr1;
    // preload tile 0 (normalize + write back)
    #pragma unroll
    for (int k = 0; k < 4; k++) {
        float* ap = abase + (size_t)(16 * k) * L_SZ;
        float4 a = *(float4*)ap;
        a.x *= invl[k]; a.y *= invl[k]; a.z *= invl[k]; a.w *= invl[k];
        stg_hint4(ap, a, POL_EF);
        ar[k] = a;
    }
    vr0 = __ldg((const float4*)vbase);
    vr1 = __ldg((const float4*)(vbase + 4));
    #pragma unroll
    for (int k = 0; k < 4; k++) {
        float* at = Atb + hs * AT_H + (size_t)jc * 65 + rr + 16 * k;
        at[0]   = ar[k].x;
        at[65]  = ar[k].y;
        at[130] = ar[k].z;
        at[195] = ar[k].w;
    }
    *(float4*)(Vsb + vrow * 68 + vc)     = vr0;
    *(float4*)(Vsb + vrow * 68 + vc + 4) = vr1;
    __syncthreads();

    for (int jt = 0; jt < 8; jt++) {
        int cur = jt & 1;
        if (jt < 7) {
            int off = (jt + 1) * 32;
            #pragma unroll
            for (int k = 0; k < 4; k++) {
                float* ap = abase + (size_t)(16 * k) * L_SZ + off;
                float4 a = *(float4*)ap;
                a.x *= invl[k]; a.y *= invl[k]; a.z *= invl[k]; a.w *= invl[k];
                stg_hint4(ap, a, POL_EF);
                ar[k] = a;
            }
            vr0 = __ldg((const float4*)(vbase + (size_t)off * DM));
            vr1 = __ldg((const float4*)(vbase + (size_t)off * DM + 4));
        }
        const float* Atc = Atb + cur * AT_BUF + s * AT_H;
        const float* Vsc = Vsb + cur * VS_BUF;
        int vcol = s * 32 + w4 * 8;
        #pragma unroll
        for (int kk = 0; kk < 32; kk++) {
            float a0 = Atc[kk * 65 + lane];
            float a1 = Atc[kk * 65 + lane + 32];
            ulonglong2 vA = *(const ulonglong2*)(Vsc + kk * 68 + vcol);
            ulonglong2 vB = *(const ulonglong2*)(Vsc + kk * 68 + vcol + 4);
            unsigned long long ap0 = pk2(a0, a0);
            unsigned long long ap1 = pk2(a1, a1);
            acc[0][0] = ffma2(vA.x, ap0, acc[0][0]);
            acc[0][1] = ffma2(vA.y, ap0, acc[0][1]);
            acc[0][2] = ffma2(vB.x, ap0, acc[0][2]);
            acc[0][3] = ffma2(vB.y, ap0, acc[0][3]);
            acc[1][0] = ffma2(vA.x, ap1, acc[1][0]);
            acc[1][1] = ffma2(vA.y, ap1, acc[1][1]);
            acc[1][2] = ffma2(vB.x, ap1, acc[1][2]);
            acc[1][3] = ffma2(vB.y, ap1, acc[1][3]);
        }
        if (jt < 7) {
            int nx = cur ^ 1;
            #pragma unroll
            for (int k = 0; k < 4; k++) {
                float* at = Atb + nx * AT_BUF + hs * AT_H + (size_t)jc * 65 + rr + 16 * k;
                at[0]   = ar[k].x;
                at[65]  = ar[k].y;
                at[130] = ar[k].z;
                at[195] = ar[k].w;
            }
            *(float4*)(Vsb + nx * VS_BUF + vrow * 68 + vc)     = vr0;
            *(float4*)(Vsb + nx * VS_BUF + vrow * 68 + vc + 4) = vr1;
        }
        __syncthreads();
    }
    #pragma unroll
    for (int p = 0; p < 2; p++) {
        float4 o1, o2;
        upk2(acc[p][0], o1.x, o1.y);
        upk2(acc[p][1], o1.z, o1.w);
        upk2(acc[p][2], o2.x, o2.y);
        upk2(acc[p][3], o2.z, o2.w);
        float* op = eout + ((size_t)(b * L_SZ) + i0 + lane + 32 * p) * DM + h * DK + w4 * 8;
        *(float4*)op       = o1;
        *(float4*)(op + 4) = o2;
    }
}

// ---------------------------------------------------------------
// fc: out = (e1a+e1b+e1c+e1d+emb2) @ fc_w^T + fc_b + residual
// ---------------------------------------------------------------
__global__ void fc_kernel(const float* __restrict__ Bm,
                          const float* __restrict__ fcb,
                          const float* __restrict__ res,
                          float* __restrict__ C)
{
    __shared__ float As[2][16][64];
    __shared__ float Bs[2][16][64];
    int tid = threadIdx.x;
    int tx = tid & 15, ty = tid >> 4;
    int m0 = blockIdx.y * 64, n0 = blockIdx.x * 64;
    int lr = tid >> 2, lc = (tid & 3) * 4;
    unsigned long long acc[4][2];
    #pragma unroll
    for (int i = 0; i < 4; i++) { acc[i][0] = 0ull; acc[i][1] = 0ull; }

    size_t abase = (size_t)(m0 + lr) * DM + lc;
    const float* Bptr = Bm + (size_t)(n0 + lr) * DM + lc;

    {
        float4 a1 = *(const float4*)(g_e1a + abase);
        float4 a3 = *(const float4*)(g_e1b + abase);
        float4 a4 = *(const float4*)(g_e1c + abase);
        float4 a5 = *(const float4*)(g_e1d + abase);
        float4 a2 = *(const float4*)(g_emb2 + abase);
        float4 bv = *(const float4*)Bptr;
        As[0][lc + 0][lr] = a1.x + a3.x + a4.x + a5.x + a2.x;
        As[0][lc + 1][lr] = a1.y + a3.y + a4.y + a5.y + a2.y;
        As[0][lc + 2][lr] = a1.z + a3.z + a4.z + a5.z + a2.z;
        As[0][lc + 3][lr] = a1.w + a3.w + a4.w + a5.w + a2.w;
        Bs[0][lc + 0][lr] = bv.x; Bs[0][lc + 1][lr] = bv.y; Bs[0][lc + 2][lr] = bv.z; Bs[0][lc + 3][lr] = bv.w;
    }
    __syncthreads();

    for (int t = 0; t < 16; t++) {
        int cur = t & 1;
        float4 asum, bv2;
        if (t < 15) {
            size_t aoff = abase + (t + 1) * 16;
            float4 a1 = *(const float4*)(g_e1a + aoff);
            float4 a3 = *(const float4*)(g_e1b + aoff);
            float4 a4 = *(const float4*)(g_e1c + aoff);
            float4 a5 = *(const float4*)(g_e1d + aoff);
            float4 a2 = *(const float4*)(g_emb2 + aoff);
            asum.x = a1.x + a3.x + a4.x + a5.x + a2.x;
            asum.y = a1.y + a3.y + a4.y + a5.y + a2.y;
            asum.z = a1.z + a3.z + a4.z + a5.z + a2.z;
            asum.w = a1.w + a3.w + a4.w + a5.w + a2.w;
            bv2 = *(const float4*)(Bptr + (t + 1) * 16);
        }
        #pragma unroll
        for (int kk = 0; kk < 16; kk++) {
            float4 a = *(const float4*)&As[cur][kk][ty * 4];
            ulonglong2 b2 = *(const ulonglong2*)&Bs[cur][kk][tx * 4];
            unsigned long long ap;
            ap = pk2(a.x, a.x);
            acc[0][0] = ffma2(b2.x, ap, acc[0][0]);
            acc[0][1] = ffma2(b2.y, ap, acc[0][1]);
            ap = pk2(a.y, a.y);
            acc[1][0] = ffma2(b2.x, ap, acc[1][0]);
            acc[1][1] = ffma2(b2.y, ap, acc[1][1]);
            ap = pk2(a.z, a.z);
            acc[2][0] = ffma2(b2.x, ap, acc[2][0]);
            acc[2][1] = ffma2(b2.y, ap, acc[2][1]);
            ap = pk2(a.w, a.w);
            acc[3][0] = ffma2(b2.x, ap, acc[3][0]);
            acc[3][1] = ffma2(b2.y, ap, acc[3][1]);
        }
        if (t < 15) {
            int nx = cur ^ 1;
            As[nx][lc + 0][lr] = asum.x; As[nx][lc + 1][lr] = asum.y;
            As[nx][lc + 2][lr] = asum.z; As[nx][lc + 3][lr] = asum.w;
            Bs[nx][lc + 0][lr] = bv2.x; Bs[nx][lc + 1][lr] = bv2.y;
            Bs[nx][lc + 2][lr] = bv2.z; Bs[nx][lc + 3][lr] = bv2.w;
        }
        __syncthreads();
    }
    #pragma unroll
    for (int i = 0; i < 4; i++) {
        int m = m0 + ty * 4 + i;
        float r0, r1, r2, r3;
        upk2(acc[i][0], r0, r1);
        upk2(acc[i][1], r2, r3);
        int n = n0 + tx * 4;
        const float4 rv = *(const float4*)(res + (size_t)m * DM + n);
        const float4 bb = *(const float4*)(fcb + n);
        float4 o;
        o.x = r0 + bb.x + rv.x;
        o.y = r1 + bb.y + rv.y;
        o.z = r2 + bb.z + rv.z;
        o.w = r3 + bb.w + rv.w;
        *(float4*)(C + (size_t)m * DM + n) = o;
    }
}

// ---------------------------------------------------------------
extern "C" void kernel_launch(void* const* d_in, const int* in_sizes, int n_in,
                              void* d_out, int out_size)
{
    const float* h    = (const float*)d_in[0];
    const float* bias = (const float*)d_in[1];
    const float* w_qs = (const float*)d_in[2];
    const float* w_ks = (const float*)d_in[3];
    const float* w_vs = (const float*)d_in[4];
    const float* ln_g = (const float*)d_in[5];
    const float* ln_b = (const float*)d_in[6];
    const float* fc_w = (const float*)d_in[7];
    const float* fc_b = (const float*)d_in[8];

    float* out  = (float*)d_out;                       // (B, L, 256)
    float* attn = out + (size_t)B_SZ * L_SZ * DM;      // (H, B, L, L)

    const int SMEM_S2 = (512 + 4224 + 1536 + 32 + 512) * sizeof(float);  // 27264 B
    cudaFuncSetAttribute(s2_kernel, cudaFuncAttributeMaxDynamicSharedMemorySize, SMEM_S2);
    cudaFuncSetAttribute(e1_kernel, cudaFuncAttributeMaxDynamicSharedMemorySize, (int)E1_SMEM);

    // 1. LayerNorm
    ln_kernel<<<NROWS, 256>>>(h, ln_g, ln_b);

    // 2. QKV projections (q pre-scaled), double-buffered
    qkv_kernel<<<dim3(12, NROWS / 64), 256>>>(w_qs, w_ks, w_vs);

    // 3. attn1 raw scores (evict_last stores)
    s1_kernel<<<dim3(16, 16, 16), 256>>>(attn);

    // 4. fused s2 (full grid, hoisted loads, L2 policies)
    s2_kernel<<<NROWS / 2, 128, SMEM_S2>>>(bias, attn);

    // 5. emb1 quarters = attn @ v (2 heads/CTA, 8 d/warp), normalize in place
    e1_kernel<<<dim3(16, 8, 4), 256, E1_SMEM>>>(attn);

    // 6. out = (e1a+e1b+e1c+e1d+emb2) @ fc_w^T + fc_b + residual
    fc_kernel<<<dim3(4, NROWS / 64), 256>>>(fc_w, fc_b, h, out);
}